// round 5
// baseline (speedup 1.0000x reference)
#include <cuda_runtime.h>
#include <cstdint>

#define N_NODES 100000
#define D 128
#define N_EDGES 1600000
#define TILE 64
#define NTILES ((N_NODES + TILE - 1) / TILE)     // 1563
#define NB_SCAN ((N_NODES + 255) / 256)          // 391

// Scratch (allocation-free rule: __device__ globals)
__device__ int g_cnt[N_NODES];      // counts, then reused as fill cursor
__device__ int g_rs[N_NODES + 1];   // CSR row_start
__device__ int g_esrc[N_EDGES];     // CSR: src node per (dst-grouped) edge
__device__ int g_bsum[512];         // scan block sums
__device__ int g_is64;

// ---------------- packed f32x2 helpers (validated in R3) ----------------
__device__ __forceinline__ unsigned long long fma2(unsigned long long a,
                                                   unsigned long long b,
                                                   unsigned long long c) {
    unsigned long long d;
    asm("fma.rn.f32x2 %0, %1, %2, %3;" : "=l"(d) : "l"(a), "l"(b), "l"(c));
    return d;
}
__device__ __forceinline__ unsigned long long dup2(float a) {
    unsigned long long d;
    asm("mov.b64 %0, {%1, %1};" : "=l"(d) : "f"(a));
    return d;
}
__device__ __forceinline__ float2 unpack2(unsigned long long v) {
    float2 r;
    asm("mov.b64 {%0, %1}, %2;" : "=f"(r.x), "=f"(r.y) : "l"(v));
    return r;
}

// ---------------- kernel 0: index dtype sniff (validated in R3) ----------------
__global__ void sniff_kernel(const void* __restrict__ src) {
    if (threadIdx.x == 0 && blockIdx.x == 0) {
        const long long* p = (const long long*)src;
        int ok = 1;
        #pragma unroll 1
        for (int i = 0; i < 64; i++) {
            long long v = p[i];
            if (v < 0 || v >= N_NODES) { ok = 0; break; }
        }
        g_is64 = ok;
    }
}

__device__ __forceinline__ void load_edge(const void* src_raw, const void* dst_raw,
                                          int e, int is64, int& s, int& d) {
    if (is64) {
        s = (int)((const long long*)src_raw)[e];
        d = (int)((const long long*)dst_raw)[e];
    } else {
        s = ((const int*)src_raw)[e];
        d = ((const int*)dst_raw)[e];
    }
}

// ---------------- kernel 1: zero counts ----------------
__global__ void zero_cnt_kernel() {
    int i = blockIdx.x * blockDim.x + threadIdx.x;
    if (i < N_NODES) g_cnt[i] = 0;
}

// ---------------- kernel 2: count in-degrees ----------------
__global__ void count_kernel(const void* __restrict__ src_raw,
                             const void* __restrict__ dst_raw) {
    const int is64 = g_is64;
    int idx = blockIdx.x * blockDim.x + threadIdx.x;
    int stride = gridDim.x * blockDim.x;
    for (int e = idx; e < N_EDGES; e += stride) {
        int s, d;
        load_edge(src_raw, dst_raw, e, is64, s, d);
        if ((unsigned)s < N_NODES && (unsigned)d < N_NODES)
            atomicAdd(&g_cnt[d], 1);
    }
}

// ---------------- scan (3 tiny kernels) ----------------
__global__ void scan1_kernel() {
    __shared__ int sm[256];
    int gi = blockIdx.x * 256 + threadIdx.x;
    sm[threadIdx.x] = (gi < N_NODES) ? g_cnt[gi] : 0;
    __syncthreads();
    for (int off = 128; off > 0; off >>= 1) {
        if (threadIdx.x < off) sm[threadIdx.x] += sm[threadIdx.x + off];
        __syncthreads();
    }
    if (threadIdx.x == 0) g_bsum[blockIdx.x] = sm[0];
}
__global__ void scan2_kernel() {
    __shared__ int sm[512];
    int t = threadIdx.x;
    sm[t] = (t < NB_SCAN) ? g_bsum[t] : 0;
    __syncthreads();
    for (int off = 1; off < 512; off <<= 1) {
        int v = (t >= off) ? sm[t - off] : 0;
        __syncthreads();
        sm[t] += v;
        __syncthreads();
    }
    int ex = (t == 0) ? 0 : sm[t - 1];
    if (t < NB_SCAN) g_bsum[t] = ex;
    if (t == NB_SCAN) g_rs[N_NODES] = sm[NB_SCAN - 1];
}
__global__ void scan3_kernel() {
    __shared__ int sm[256];
    int b = blockIdx.x, t = threadIdx.x;
    int gi = b * 256 + t;
    int c = (gi < N_NODES) ? g_cnt[gi] : 0;
    sm[t] = c;
    __syncthreads();
    for (int off = 1; off < 256; off <<= 1) {
        int v = (t >= off) ? sm[t - off] : 0;
        __syncthreads();
        sm[t] += v;
        __syncthreads();
    }
    int ex = sm[t] - c;  // exclusive within block
    if (gi < N_NODES) {
        g_rs[gi] = g_bsum[b] + ex;
        g_cnt[gi] = 0;   // reset -> fill cursor
    }
}

// ---------------- kernel 3: fill CSR ----------------
__global__ void fill_kernel(const void* __restrict__ src_raw,
                            const void* __restrict__ dst_raw) {
    const int is64 = g_is64;
    int idx = blockIdx.x * blockDim.x + threadIdx.x;
    int stride = gridDim.x * blockDim.x;
    for (int e = idx; e < N_EDGES; e += stride) {
        int s, d;
        load_edge(src_raw, dst_raw, e, is64, s, d);
        if ((unsigned)s < N_NODES && (unsigned)d < N_NODES) {
            int pos = atomicAdd(&g_cnt[d], 1);
            g_esrc[g_rs[d] + pos] = s;
        }
    }
}

// ---------------- kernel 4: fused gather + dual GEMM ----------------
// Per 64-row tile: gather neighbor means into smem (CSR, no atomics),
// then out = Xs @ Ws + Xn @ Wn with 8x4 register blocking, f32x2 FMA.
// SMEM: Ws 64KB + Wn 64KB + Xs 32KB + Xn 32KB = 192KB. 256 threads, 1 CTA/SM.
__global__ __launch_bounds__(256, 1)
void fused_kernel(const float* __restrict__ h,
                  const float* __restrict__ Ws,
                  const float* __restrict__ Wn,
                  float* __restrict__ out) {
    extern __shared__ float sm[];
    float* sWs = sm;             // 128x128
    float* sWn = sm + 16384;     // 128x128
    float* sXs = sm + 32768;     // 64x128
    float* sXn = sm + 40960;     // 64x128

    int tid = threadIdx.x, wid = tid >> 5, lane = tid & 31;

    // W into smem once (persistent CTAs)
    for (int i = tid; i < 16384 / 4; i += 256) {
        reinterpret_cast<float4*>(sWs)[i] = reinterpret_cast<const float4*>(Ws)[i];
        reinterpret_cast<float4*>(sWn)[i] = reinterpret_cast<const float4*>(Wn)[i];
    }

    int cg = tid & 31;   // cols [cg*4, cg*4+4)
    int rg = tid >> 5;   // rows [rg*8, rg*8+8)
    int c0 = cg * 4;
    int r0 = rg * 8;

    for (int t = blockIdx.x; t < NTILES; t += gridDim.x) {
        int tb = t * TILE;
        __syncthreads();  // prev GEMM done with smem (and W-load on 1st iter)

        // ---- gather phase: warp wid handles 8 rows ----
        #pragma unroll 1
        for (int rr = 0; rr < 8; rr++) {
            int r = wid * 8 + rr;
            int row = tb + r;
            float4 self = make_float4(0.f, 0.f, 0.f, 0.f);
            float4 acc  = make_float4(0.f, 0.f, 0.f, 0.f);
            float inv = 0.f;
            if (row < N_NODES) {
                self = reinterpret_cast<const float4*>(h + (size_t)row * D)[lane];
                int beg = g_rs[row], end = g_rs[row + 1];
                inv = 1.0f / fmaxf((float)(end - beg), 1.0f);
                int e = beg;
                #pragma unroll 1
                for (; e + 4 <= end; e += 4) {  // MLP=4 independent row loads
                    int s0 = g_esrc[e + 0], s1 = g_esrc[e + 1];
                    int s2 = g_esrc[e + 2], s3 = g_esrc[e + 3];
                    float4 v0 = reinterpret_cast<const float4*>(h + (size_t)s0 * D)[lane];
                    float4 v1 = reinterpret_cast<const float4*>(h + (size_t)s1 * D)[lane];
                    float4 v2 = reinterpret_cast<const float4*>(h + (size_t)s2 * D)[lane];
                    float4 v3 = reinterpret_cast<const float4*>(h + (size_t)s3 * D)[lane];
                    acc.x += (v0.x + v1.x) + (v2.x + v3.x);
                    acc.y += (v0.y + v1.y) + (v2.y + v3.y);
                    acc.z += (v0.z + v1.z) + (v2.z + v3.z);
                    acc.w += (v0.w + v1.w) + (v2.w + v3.w);
                }
                #pragma unroll 1
                for (; e < end; e++) {
                    int s0 = g_esrc[e];
                    float4 v0 = reinterpret_cast<const float4*>(h + (size_t)s0 * D)[lane];
                    acc.x += v0.x; acc.y += v0.y; acc.z += v0.z; acc.w += v0.w;
                }
            }
            reinterpret_cast<float4*>(sXs + r * D)[lane] = self;
            reinterpret_cast<float4*>(sXn + r * D)[lane] =
                make_float4(acc.x * inv, acc.y * inv, acc.z * inv, acc.w * inv);
        }
        __syncthreads();

        // ---- GEMM phase: 8 rows x 4 cols per thread ----
        unsigned long long accu[8][2];
        #pragma unroll
        for (int i = 0; i < 8; i++) { accu[i][0] = 0ull; accu[i][1] = 0ull; }

        #pragma unroll 1
        for (int kk = 0; kk < D; kk += 4) {
            float4 as[8], an[8];
            #pragma unroll
            for (int i = 0; i < 8; i++) {
                as[i] = *reinterpret_cast<const float4*>(sXs + (r0 + i) * D + kk);
                an[i] = *reinterpret_cast<const float4*>(sXn + (r0 + i) * D + kk);
            }
            #pragma unroll
            for (int dk = 0; dk < 4; dk++) {
                ulonglong2 w2s = *reinterpret_cast<const ulonglong2*>(sWs + (kk + dk) * D + c0);
                ulonglong2 w2n = *reinterpret_cast<const ulonglong2*>(sWn + (kk + dk) * D + c0);
                #pragma unroll
                for (int i = 0; i < 8; i++) {
                    float a_s = reinterpret_cast<const float*>(&as[i])[dk];
                    float a_n = reinterpret_cast<const float*>(&an[i])[dk];
                    unsigned long long a2s = dup2(a_s);
                    unsigned long long a2n = dup2(a_n);
                    accu[i][0] = fma2(a2s, w2s.x, accu[i][0]);
                    accu[i][1] = fma2(a2s, w2s.y, accu[i][1]);
                    accu[i][0] = fma2(a2n, w2n.x, accu[i][0]);
                    accu[i][1] = fma2(a2n, w2n.y, accu[i][1]);
                }
            }
        }

        #pragma unroll
        for (int i = 0; i < 8; i++) {
            int row = tb + r0 + i;
            if (row < N_NODES) {
                float2 lo = unpack2(accu[i][0]);
                float2 hi = unpack2(accu[i][1]);
                *reinterpret_cast<float4*>(out + (size_t)row * D + c0) =
                    make_float4(lo.x, lo.y, hi.x, hi.y);
            }
        }
    }
}

// ---------------- launch ----------------
extern "C" void kernel_launch(void* const* d_in, const int* in_sizes, int n_in,
                              void* d_out, int out_size) {
    const float* h      = (const float*)d_in[0];
    const void*  src    = d_in[1];
    const void*  dst    = d_in[2];
    const float* Wself  = (const float*)d_in[3];
    const float* Wneigh = (const float*)d_in[4];
    float*       out    = (float*)d_out;

    static bool attr_set = false;
    if (!attr_set) {
        cudaFuncSetAttribute(fused_kernel,
                             cudaFuncAttributeMaxDynamicSharedMemorySize,
                             196608);
        attr_set = true;
    }

    sniff_kernel<<<1, 32>>>(src);
    zero_cnt_kernel<<<NB_SCAN, 256>>>();
    count_kernel<<<2048, 256>>>(src, dst);
    scan1_kernel<<<NB_SCAN, 256>>>();
    scan2_kernel<<<1, 512>>>();
    scan3_kernel<<<NB_SCAN, 256>>>();
    fill_kernel<<<2048, 256>>>(src, dst);
    fused_kernel<<<152, 256, 196608>>>(h, Wself, Wneigh, out);
}

// round 6
// speedup vs baseline: 1.4293x; 1.4293x over previous
#include <cuda_runtime.h>
#include <cstdint>

#define N_NODES 100000
#define D 128
#define N_EDGES 1600000
#define TILE 32
#define NTILES (N_NODES / TILE)                  // 3125 exact (100000 = 32*3125)
#define NB_SCAN ((N_NODES + 255) / 256)          // 391

// Scratch (allocation-free rule: __device__ globals)
__device__ int g_cnt[N_NODES];      // counts, then reused as fill cursor
__device__ int g_rs[N_NODES + 1];   // CSR row_start
__device__ int g_esrc[N_EDGES];     // CSR: src node per (dst-grouped) edge
__device__ int g_bsum[512];         // scan block sums
__device__ int g_is64;

// ---------------- packed f32x2 helpers (validated R3/R4) ----------------
__device__ __forceinline__ unsigned long long fma2(unsigned long long a,
                                                   unsigned long long b,
                                                   unsigned long long c) {
    unsigned long long d;
    asm("fma.rn.f32x2 %0, %1, %2, %3;" : "=l"(d) : "l"(a), "l"(b), "l"(c));
    return d;
}
__device__ __forceinline__ unsigned long long dup2(float a) {
    unsigned long long d;
    asm("mov.b64 %0, {%1, %1};" : "=l"(d) : "f"(a));
    return d;
}
__device__ __forceinline__ float2 unpack2(unsigned long long v) {
    float2 r;
    asm("mov.b64 {%0, %1}, %2;" : "=f"(r.x), "=f"(r.y) : "l"(v));
    return r;
}

// ---------------- kernel 0: index dtype sniff (validated) ----------------
__global__ void sniff_kernel(const void* __restrict__ src) {
    if (threadIdx.x == 0 && blockIdx.x == 0) {
        const long long* p = (const long long*)src;
        int ok = 1;
        #pragma unroll 1
        for (int i = 0; i < 64; i++) {
            long long v = p[i];
            if (v < 0 || v >= N_NODES) { ok = 0; break; }
        }
        g_is64 = ok;
    }
}

__device__ __forceinline__ void load_edge(const void* src_raw, const void* dst_raw,
                                          int e, int is64, int& s, int& d) {
    if (is64) {
        s = (int)((const long long*)src_raw)[e];
        d = (int)((const long long*)dst_raw)[e];
    } else {
        s = ((const int*)src_raw)[e];
        d = ((const int*)dst_raw)[e];
    }
}

// ---------------- CSR build (validated R4) ----------------
__global__ void zero_cnt_kernel() {
    int i = blockIdx.x * blockDim.x + threadIdx.x;
    if (i < N_NODES) g_cnt[i] = 0;
}

__global__ void count_kernel(const void* __restrict__ src_raw,
                             const void* __restrict__ dst_raw) {
    const int is64 = g_is64;
    int idx = blockIdx.x * blockDim.x + threadIdx.x;
    int stride = gridDim.x * blockDim.x;
    for (int e = idx; e < N_EDGES; e += stride) {
        int s, d;
        load_edge(src_raw, dst_raw, e, is64, s, d);
        if ((unsigned)s < N_NODES && (unsigned)d < N_NODES)
            atomicAdd(&g_cnt[d], 1);
    }
}

__global__ void scan1_kernel() {
    __shared__ int sm[256];
    int gi = blockIdx.x * 256 + threadIdx.x;
    sm[threadIdx.x] = (gi < N_NODES) ? g_cnt[gi] : 0;
    __syncthreads();
    for (int off = 128; off > 0; off >>= 1) {
        if (threadIdx.x < off) sm[threadIdx.x] += sm[threadIdx.x + off];
        __syncthreads();
    }
    if (threadIdx.x == 0) g_bsum[blockIdx.x] = sm[0];
}
__global__ void scan2_kernel() {
    __shared__ int sm[512];
    int t = threadIdx.x;
    sm[t] = (t < NB_SCAN) ? g_bsum[t] : 0;
    __syncthreads();
    for (int off = 1; off < 512; off <<= 1) {
        int v = (t >= off) ? sm[t - off] : 0;
        __syncthreads();
        sm[t] += v;
        __syncthreads();
    }
    int ex = (t == 0) ? 0 : sm[t - 1];
    if (t < NB_SCAN) g_bsum[t] = ex;
    if (t == NB_SCAN) g_rs[N_NODES] = sm[NB_SCAN - 1];
}
__global__ void scan3_kernel() {
    __shared__ int sm[256];
    int b = blockIdx.x, t = threadIdx.x;
    int gi = b * 256 + t;
    int c = (gi < N_NODES) ? g_cnt[gi] : 0;
    sm[t] = c;
    __syncthreads();
    for (int off = 1; off < 256; off <<= 1) {
        int v = (t >= off) ? sm[t - off] : 0;
        __syncthreads();
        sm[t] += v;
        __syncthreads();
    }
    int ex = sm[t] - c;
    if (gi < N_NODES) {
        g_rs[gi] = g_bsum[b] + ex;
        g_cnt[gi] = 0;
    }
}

__global__ void fill_kernel(const void* __restrict__ src_raw,
                            const void* __restrict__ dst_raw) {
    const int is64 = g_is64;
    int idx = blockIdx.x * blockDim.x + threadIdx.x;
    int stride = gridDim.x * blockDim.x;
    for (int e = idx; e < N_EDGES; e += stride) {
        int s, d;
        load_edge(src_raw, dst_raw, e, is64, s, d);
        if ((unsigned)s < N_NODES && (unsigned)d < N_NODES) {
            int pos = atomicAdd(&g_cnt[d], 1);
            g_esrc[g_rs[d] + pos] = s;
        }
    }
}

// ---------------- fused kernel: warp-specialized ping-pong ----------------
// 384 threads: warps 0-3 compute (32-row tile GEMM, 8 rows x 4 cols/thread),
//              warps 4-11 gather (CSR mean into next buffer, 4 rows/warp).
// SMEM floats: sWs[16384] sWn[16384] | buf0: Xs[4096] Xn[4096] | buf1: same.
// Total 49152 floats = 192 KB. 1 CTA/SM. One __syncthreads per tile.
__global__ __launch_bounds__(384, 1)
void fused_kernel(const float* __restrict__ h,
                  const float* __restrict__ Ws,
                  const float* __restrict__ Wn,
                  float* __restrict__ out) {
    extern __shared__ float sm[];
    float* sWs = sm;
    float* sWn = sm + 16384;
    float* sX  = sm + 32768;  // [2][2][32][128]: buf, self/neigh, row, col

    int tid = threadIdx.x, wid = tid >> 5, lane = tid & 31;
    const bool is_gather = (wid >= 4);

    // ---- gather helper lambda ----
    auto fill_tile = [&](int tile, int buf) {
        float* bXs = sX + buf * 8192;
        float* bXn = bXs + 4096;
        int gwid = wid - 4;  // 0..7
        #pragma unroll 1
        for (int rr = 0; rr < 4; rr++) {
            int r = gwid * 4 + rr;
            int row = tile * TILE + r;
            float4 self = reinterpret_cast<const float4*>(h + (size_t)row * D)[lane];
            int beg = g_rs[row], end = g_rs[row + 1];
            float inv = 1.0f / fmaxf((float)(end - beg), 1.0f);
            float4 acc = make_float4(0.f, 0.f, 0.f, 0.f);
            int e = beg;
            #pragma unroll 1
            for (; e + 8 <= end; e += 8) {   // MLP=8
                int si[8];
                #pragma unroll
                for (int q = 0; q < 8; q++) si[q] = g_esrc[e + q];
                float4 v[8];
                #pragma unroll
                for (int q = 0; q < 8; q++)
                    v[q] = reinterpret_cast<const float4*>(h + (size_t)si[q] * D)[lane];
                #pragma unroll
                for (int q = 0; q < 8; q++) {
                    acc.x += v[q].x; acc.y += v[q].y;
                    acc.z += v[q].z; acc.w += v[q].w;
                }
            }
            #pragma unroll 1
            for (; e < end; e++) {
                int s0 = g_esrc[e];
                float4 v0 = reinterpret_cast<const float4*>(h + (size_t)s0 * D)[lane];
                acc.x += v0.x; acc.y += v0.y; acc.z += v0.z; acc.w += v0.w;
            }
            reinterpret_cast<float4*>(bXs + r * D)[lane] = self;
            reinterpret_cast<float4*>(bXn + r * D)[lane] =
                make_float4(acc.x * inv, acc.y * inv, acc.z * inv, acc.w * inv);
        }
    };

    // ---- prologue: compute warps load W, gather warps fill buf0 ----
    int t = blockIdx.x;
    if (is_gather) {
        if (t < NTILES) fill_tile(t, 0);
    } else {
        // 128 threads load 32768 float4 -> 256 each... actually 8192 float4 per matrix
        for (int i = tid; i < 4096; i += 128) {
            reinterpret_cast<float4*>(sWs)[i] = reinterpret_cast<const float4*>(Ws)[i];
            reinterpret_cast<float4*>(sWn)[i] = reinterpret_cast<const float4*>(Wn)[i];
        }
    }
    __syncthreads();

    int p = 0;
    int c0 = lane * 4;       // compute cols
    int r0 = wid * 8;        // compute rows (wid 0..3)

    for (; t < NTILES; t += gridDim.x) {
        if (is_gather) {
            int tn = t + gridDim.x;
            if (tn < NTILES) fill_tile(tn, p ^ 1);
        } else {
            float* bXs = sX + p * 8192;
            float* bXn = bXs + 4096;

            unsigned long long accu[8][2];
            #pragma unroll
            for (int i = 0; i < 8; i++) { accu[i][0] = 0ull; accu[i][1] = 0ull; }

            #pragma unroll 1
            for (int kk = 0; kk < D; kk += 4) {
                float4 as[8], an[8];
                #pragma unroll
                for (int i = 0; i < 8; i++) {
                    as[i] = *reinterpret_cast<const float4*>(bXs + (r0 + i) * D + kk);
                    an[i] = *reinterpret_cast<const float4*>(bXn + (r0 + i) * D + kk);
                }
                #pragma unroll
                for (int dk = 0; dk < 4; dk++) {
                    ulonglong2 w2s = *reinterpret_cast<const ulonglong2*>(sWs + (kk + dk) * D + c0);
                    ulonglong2 w2n = *reinterpret_cast<const ulonglong2*>(sWn + (kk + dk) * D + c0);
                    #pragma unroll
                    for (int i = 0; i < 8; i++) {
                        float a_s = reinterpret_cast<const float*>(&as[i])[dk];
                        float a_n = reinterpret_cast<const float*>(&an[i])[dk];
                        unsigned long long a2s = dup2(a_s);
                        unsigned long long a2n = dup2(a_n);
                        accu[i][0] = fma2(a2s, w2s.x, accu[i][0]);
                        accu[i][1] = fma2(a2s, w2s.y, accu[i][1]);
                        accu[i][0] = fma2(a2n, w2n.x, accu[i][0]);
                        accu[i][1] = fma2(a2n, w2n.y, accu[i][1]);
                    }
                }
            }

            #pragma unroll
            for (int i = 0; i < 8; i++) {
                int row = t * TILE + r0 + i;
                float2 lo = unpack2(accu[i][0]);
                float2 hi = unpack2(accu[i][1]);
                *reinterpret_cast<float4*>(out + (size_t)row * D + c0) =
                    make_float4(lo.x, lo.y, hi.x, hi.y);
            }
        }
        __syncthreads();
        p ^= 1;
    }
}

// ---------------- launch ----------------
extern "C" void kernel_launch(void* const* d_in, const int* in_sizes, int n_in,
                              void* d_out, int out_size) {
    const float* h      = (const float*)d_in[0];
    const void*  src    = d_in[1];
    const void*  dst    = d_in[2];
    const float* Wself  = (const float*)d_in[3];
    const float* Wneigh = (const float*)d_in[4];
    float*       out    = (float*)d_out;

    static bool attr_set = false;
    if (!attr_set) {
        cudaFuncSetAttribute(fused_kernel,
                             cudaFuncAttributeMaxDynamicSharedMemorySize,
                             196608);
        attr_set = true;
    }

    sniff_kernel<<<1, 32>>>(src);
    zero_cnt_kernel<<<NB_SCAN, 256>>>();
    count_kernel<<<2048, 256>>>(src, dst);
    scan1_kernel<<<NB_SCAN, 256>>>();
    scan2_kernel<<<1, 512>>>();
    scan3_kernel<<<NB_SCAN, 256>>>();
    fill_kernel<<<2048, 256>>>(src, dst);
    fused_kernel<<<152, 384, 196608>>>(h, Wself, Wneigh, out);
}